// round 5
// baseline (speedup 1.0000x reference)
#include <cuda_runtime.h>
#include <cstdint>

#define N_NODES 100000
#define N_EDGES 1600000
#define F 64

// ---------------- static device scratch ----------------
__device__ int   g_deg[N_NODES];
__device__ int   g_off[N_NODES + 1];
__device__ int   g_cursor[N_NODES];
__device__ int   g_bsum[128];
__device__ int2  g_csr[N_EDGES];               // packed {src, float_bits(e)}
__device__ float g_deginv[N_NODES];
__device__ float g_tp1[(size_t)N_NODES * 128]; // [in@W1_top+b1 | in@W1_bot]
__device__ float g_h1[(size_t)N_NODES * F];    // layer-1 output
__device__ float g_hN[(size_t)N_NODES * F];    // tp2 = [h1@W2_top+b2 | h1@W2_bot]

// ---------------- f32x2 packed-FMA helpers (Blackwell FFMA2) ----------------
__device__ __forceinline__ unsigned long long pack2(float a) {
    unsigned long long r;
    asm("mov.b64 %0, {%1, %1};" : "=l"(r) : "f"(a));
    return r;
}
__device__ __forceinline__ void ffma2(unsigned long long& d,
                                      unsigned long long a, unsigned long long b) {
    asm("fma.rn.f32x2 %0, %1, %2, %0;" : "+l"(d) : "l"(a), "l"(b));
}
__device__ __forceinline__ float2 unpack2(unsigned long long v) {
    float lo, hi;
    asm("mov.b64 {%0, %1}, %2;" : "=f"(lo), "=f"(hi) : "l"(v));
    return make_float2(lo, hi);
}

// ---------------- CSR build ----------------
__global__ void k_deg(const int4* __restrict__ dst4) {
    int i = blockIdx.x * blockDim.x + threadIdx.x;
    if (i < N_EDGES / 4) {
        int4 d = dst4[i];
        atomicAdd(&g_deg[d.x], 1);
        atomicAdd(&g_deg[d.y], 1);
        atomicAdd(&g_deg[d.z], 1);
        atomicAdd(&g_deg[d.w], 1);
    }
}

__global__ void k_scan_local() {
    __shared__ int sh[1024];
    int i = blockIdx.x * 1024 + threadIdx.x;
    int v = (i < N_NODES) ? g_deg[i] : 0;
    sh[threadIdx.x] = v;
    __syncthreads();
#pragma unroll
    for (int off = 1; off < 1024; off <<= 1) {
        int t = 0;
        if ((int)threadIdx.x >= off) t = sh[threadIdx.x - off];
        __syncthreads();
        sh[threadIdx.x] += t;
        __syncthreads();
    }
    if (i < N_NODES) g_off[i + 1] = sh[threadIdx.x];
    if (threadIdx.x == 1023) g_bsum[blockIdx.x] = sh[1023];
}

// merged: block-prefix over g_bsum + finalize offsets + cursor + deginv
__global__ void __launch_bounds__(256) k_scan_finish() {
    __shared__ int sred[256];
    int t = threadIdx.x, b = blockIdx.x;
    int s = 0;
    for (int j = t; j < b; j += 256) s += g_bsum[j];
    sred[t] = s;
    __syncthreads();
#pragma unroll
    for (int off = 128; off > 0; off >>= 1) {
        if (t < off) sred[t] += sred[t + off];
        __syncthreads();
    }
    int prefix = sred[0];
#pragma unroll
    for (int q = 0; q < 4; q++) {
        int i = b * 1024 + q * 256 + t;
        if (i < N_NODES) {
            int val = g_off[i + 1] + prefix;
            g_off[i + 1] = val;
            int d = g_deg[i];
            g_cursor[i] = val - d;             // == final g_off[i]
            g_deginv[i] = 1.0f / (float)(d > 0 ? d : 1);
        }
    }
    if (b == 0 && t == 0) g_off[0] = 0;
}

__global__ void k_fill_csr(const int4* __restrict__ src4, const int4* __restrict__ dst4,
                           const float4* __restrict__ e4) {
    int i = blockIdx.x * blockDim.x + threadIdx.x;
    if (i < N_EDGES / 4) {
        int4 s = src4[i];
        int4 d = dst4[i];
        float4 e = e4[i];
        int p0 = atomicAdd(&g_cursor[d.x], 1);
        g_csr[p0] = make_int2(s.x, __float_as_int(e.x));
        int p1 = atomicAdd(&g_cursor[d.y], 1);
        g_csr[p1] = make_int2(s.y, __float_as_int(e.y));
        int p2 = atomicAdd(&g_cursor[d.z], 1);
        g_csr[p2] = make_int2(s.z, __float_as_int(e.z));
        int p3 = atomicAdd(&g_cursor[d.w], 1);
        g_csr[p3] = make_int2(s.w, __float_as_int(e.w));
    }
}

// ---------------- layer-1 GEMM (f32x2): tp1 = [in@W1_top + b1 | in@W1_bot] ----------------
// W1 is [128,64] row-major. NOUT=128, BM=64, K=64, 512 threads.
__global__ void __launch_bounds__(512) k_gemm_tp1(const float* __restrict__ A0,
                                                  const float* __restrict__ W1,
                                                  const float* __restrict__ b1) {
    constexpr int NOUT = 128;
    constexpr int BM = 64;
    constexpr int AP = 64;   // all lanes broadcast-read same sA[k] -> no conflicts

    __shared__ __align__(16) float sA[BM * AP];      // 16KB
    __shared__ __align__(16) float sW[64 * NOUT];    // 32KB

    int tid = threadIdx.x;
    int m0  = blockIdx.x * BM;
    int jg  = tid & 31;      // 32 groups x 4 outs = 128
    int ng  = tid >> 5;      // 16 warps x 4 nodes = 64

    unsigned long long acc[4][2];
    if (jg < 16) {           // outputs 0..63 get b1
        ulonglong2 b2v = *(const ulonglong2*)(b1 + jg * 4);
#pragma unroll
        for (int i = 0; i < 4; i++) { acc[i][0] = b2v.x; acc[i][1] = b2v.y; }
    } else {
#pragma unroll
        for (int i = 0; i < 4; i++) { acc[i][0] = 0ull; acc[i][1] = 0ull; }
    }

    // stage A: 64 nodes x 16 float4
    for (int idx = tid; idx < BM * 16; idx += 512) {
        int m = idx >> 4, kq = idx & 15;
        int gm = m0 + m;
        float4 v = make_float4(0.f, 0.f, 0.f, 0.f);
        if (gm < N_NODES) v = *(const float4*)(A0 + (size_t)gm * F + kq * 4);
        *(float4*)(sA + m * AP + kq * 4) = v;
    }
    // stage combined W: sW[k][j] = j<64 ? W1[k][j] : W1[64+k][j-64]
    for (int idx = tid; idx < 64 * NOUT / 4; idx += 512) {
        int k = idx >> 5, jq = idx & 31;
        float4 v;
        if (jq < 16) v = *(const float4*)(W1 + k * 64 + jq * 4);
        else         v = *(const float4*)(W1 + (64 + k) * 64 + (jq - 16) * 4);
        *(float4*)(sW + k * NOUT + jq * 4) = v;
    }
    __syncthreads();

    const float* a_base = sA + (ng * 4) * AP;
#pragma unroll 8
    for (int k = 0; k < 64; ++k) {
        ulonglong2 w2 = *(const ulonglong2*)(sW + k * NOUT + jg * 4);
        unsigned long long a0 = pack2(a_base[k]);
        unsigned long long a1 = pack2(a_base[AP + k]);
        unsigned long long a2 = pack2(a_base[2 * AP + k]);
        unsigned long long a3 = pack2(a_base[3 * AP + k]);
        ffma2(acc[0][0], a0, w2.x); ffma2(acc[0][1], a0, w2.y);
        ffma2(acc[1][0], a1, w2.x); ffma2(acc[1][1], a1, w2.y);
        ffma2(acc[2][0], a2, w2.x); ffma2(acc[2][1], a2, w2.y);
        ffma2(acc[3][0], a3, w2.x); ffma2(acc[3][1], a3, w2.y);
    }

#pragma unroll
    for (int i = 0; i < 4; i++) {
        int gm = m0 + ng * 4 + i;
        if (gm < N_NODES) {
            float2 lo = unpack2(acc[i][0]);
            float2 hi = unpack2(acc[i][1]);
            float4 o = make_float4(lo.x, lo.y, hi.x, hi.y);
            *(float4*)(g_tp1 + (size_t)gm * 128 + jg * 4) = o;
        }
    }
}

// ---------------- layer-1 aggregation + epilogue ----------------
// h1[n] = relu(tp1[n][0..63] + dinv * sum_e e*tp1[src][64..127])
__global__ void __launch_bounds__(256) k_agg64_relu() {
    int warp = (blockIdx.x * blockDim.x + threadIdx.x) >> 5;
    if (warp >= N_NODES) return;
    int lane = threadIdx.x & 31;
    int g = lane >> 4;      // edge sub-group 0..1
    int c = lane & 15;      // float4 slot

    const float* __restrict__ tp = (const float*)g_tp1;

    int beg = g_off[warp], end = g_off[warp + 1];
    float4 acc = make_float4(0.f, 0.f, 0.f, 0.f);
#pragma unroll 4
    for (int p = beg; p < end; p += 2) {
        int pe = p + g;
        if (pe < end) {
            int2 se = g_csr[pe];
            float ev = __int_as_float(se.y);
            float4 r = *(const float4*)(tp + (size_t)se.x * 128 + 64 + c * 4);
            acc.x = fmaf(r.x, ev, acc.x);
            acc.y = fmaf(r.y, ev, acc.y);
            acc.z = fmaf(r.z, ev, acc.z);
            acc.w = fmaf(r.w, ev, acc.w);
        }
    }
    acc.x += __shfl_xor_sync(0xffffffff, acc.x, 16);
    acc.y += __shfl_xor_sync(0xffffffff, acc.y, 16);
    acc.z += __shfl_xor_sync(0xffffffff, acc.z, 16);
    acc.w += __shfl_xor_sync(0xffffffff, acc.w, 16);
    if (g == 0) {
        float dinv = g_deginv[warp];
        float4 t = *(const float4*)(tp + (size_t)warp * 128 + c * 4);
        float4 o = make_float4(fmaxf(t.x + acc.x * dinv, 0.f),
                               fmaxf(t.y + acc.y * dinv, 0.f),
                               fmaxf(t.z + acc.z * dinv, 0.f),
                               fmaxf(t.w + acc.w * dinv, 0.f));
        *(float4*)(g_h1 + (size_t)warp * F + c * 4) = o;
    }
}

// ---------------- layer-2 GEMM (f32x2, combined): tp2 = [h1@W2_top + b2 | h1@W2_bot] ----------------
__global__ void __launch_bounds__(256) k_gemm2(const float* __restrict__ W2,
                                               const float* __restrict__ b2) {
    constexpr int NOUT = 64;   // 32 top | 32 bottom
    constexpr int BM = 64;
    constexpr int JG = NOUT / 4;   // 16
    constexpr int NT = 256;
    constexpr int AP = 68;

    __shared__ __align__(16) float sA[BM * AP];
    __shared__ __align__(16) float sW[64 * NOUT];

    int tid = threadIdx.x;
    int m0  = blockIdx.x * BM;
    int jg  = tid % JG;
    int ng  = tid / JG;

    unsigned long long acc[4][2];
    if (jg < 8) {
        ulonglong2 b2v = *(const ulonglong2*)(b2 + jg * 4);
#pragma unroll
        for (int i = 0; i < 4; i++) { acc[i][0] = b2v.x; acc[i][1] = b2v.y; }
    } else {
#pragma unroll
        for (int i = 0; i < 4; i++) { acc[i][0] = 0ull; acc[i][1] = 0ull; }
    }

    for (int idx = tid; idx < BM * 16; idx += NT) {
        int m = idx >> 4, kq = idx & 15;
        int gm = m0 + m;
        float4 v = make_float4(0.f, 0.f, 0.f, 0.f);
        if (gm < N_NODES) v = *(const float4*)(g_h1 + (size_t)gm * F + kq * 4);
        *(float4*)(sA + m * AP + kq * 4) = v;
    }
    for (int idx = tid; idx < 64 * NOUT / 4; idx += NT) {
        int k = idx >> 4, jq = idx & 15;
        float4 v;
        if (jq < 8) v = *(const float4*)(W2 + k * 32 + jq * 4);
        else        v = *(const float4*)(W2 + (64 + k) * 32 + (jq - 8) * 4);
        *(float4*)(sW + k * NOUT + jq * 4) = v;
    }
    __syncthreads();

    const float* a_base = sA + (ng * 4) * AP;
#pragma unroll 8
    for (int k = 0; k < 64; ++k) {
        ulonglong2 w2 = *(const ulonglong2*)(sW + k * NOUT + jg * 4);
        unsigned long long a0 = pack2(a_base[k]);
        unsigned long long a1 = pack2(a_base[AP + k]);
        unsigned long long a2 = pack2(a_base[2 * AP + k]);
        unsigned long long a3 = pack2(a_base[3 * AP + k]);
        ffma2(acc[0][0], a0, w2.x); ffma2(acc[0][1], a0, w2.y);
        ffma2(acc[1][0], a1, w2.x); ffma2(acc[1][1], a1, w2.y);
        ffma2(acc[2][0], a2, w2.x); ffma2(acc[2][1], a2, w2.y);
        ffma2(acc[3][0], a3, w2.x); ffma2(acc[3][1], a3, w2.y);
    }

#pragma unroll
    for (int i = 0; i < 4; i++) {
        int gm = m0 + ng * 4 + i;
        if (gm < N_NODES) {
            float2 lo = unpack2(acc[i][0]);
            float2 hi = unpack2(acc[i][1]);
            float4 o = make_float4(lo.x, lo.y, hi.x, hi.y);
            *(float4*)(g_hN + (size_t)gm * NOUT + jg * 4) = o;
        }
    }
}

// ---------------- layer-2 aggregation + epilogue ----------------
// out[n][j] = tp2[n][j] + dinv * sum_e e*tp2[src][32+j]
__global__ void __launch_bounds__(256) k_agg32_out(float* __restrict__ out) {
    int warp = (blockIdx.x * blockDim.x + threadIdx.x) >> 5;
    if (warp >= N_NODES) return;
    int lane = threadIdx.x & 31;
    int g = lane >> 3;      // edge sub-group 0..3
    int c = lane & 7;       // float4 slot

    const float* __restrict__ tp = (const float*)g_hN;

    int beg = g_off[warp], end = g_off[warp + 1];
    float4 acc = make_float4(0.f, 0.f, 0.f, 0.f);
#pragma unroll 4
    for (int p = beg; p < end; p += 4) {
        int pe = p + g;
        if (pe < end) {
            int2 se = g_csr[pe];
            float ev = __int_as_float(se.y);
            float4 r = *(const float4*)(tp + (size_t)se.x * 64 + 32 + c * 4);
            acc.x = fmaf(r.x, ev, acc.x);
            acc.y = fmaf(r.y, ev, acc.y);
            acc.z = fmaf(r.z, ev, acc.z);
            acc.w = fmaf(r.w, ev, acc.w);
        }
    }
    acc.x += __shfl_xor_sync(0xffffffff, acc.x, 8);
    acc.y += __shfl_xor_sync(0xffffffff, acc.y, 8);
    acc.z += __shfl_xor_sync(0xffffffff, acc.z, 8);
    acc.w += __shfl_xor_sync(0xffffffff, acc.w, 8);
    acc.x += __shfl_xor_sync(0xffffffff, acc.x, 16);
    acc.y += __shfl_xor_sync(0xffffffff, acc.y, 16);
    acc.z += __shfl_xor_sync(0xffffffff, acc.z, 16);
    acc.w += __shfl_xor_sync(0xffffffff, acc.w, 16);
    if (g == 0) {
        float dinv = g_deginv[warp];
        float4 t = *(const float4*)(tp + (size_t)warp * 64 + c * 4);
        float4 o = make_float4(t.x + acc.x * dinv, t.y + acc.y * dinv,
                               t.z + acc.z * dinv, t.w + acc.w * dinv);
        *(float4*)(out + (size_t)warp * 32 + c * 4) = o;
    }
}

// ---------------- launch ----------------
extern "C" void kernel_launch(void* const* d_in, const int* in_sizes, int n_in,
                              void* d_out, int out_size) {
    const float* in_feat   = (const float*)d_in[0];
    const float* edge_feat = (const float*)d_in[1];
    const int*   src       = (const int*)d_in[2];
    const int*   dst       = (const int*)d_in[3];
    const float* W1        = (const float*)d_in[4];
    const float* b1        = (const float*)d_in[5];
    const float* W2        = (const float*)d_in[6];
    const float* b2        = (const float*)d_in[7];
    float*       out       = (float*)d_out;

    // one-time host resources (created on the non-captured correctness call)
    static cudaStream_t s2 = nullptr;
    static cudaEvent_t ev0 = nullptr, ev1 = nullptr;
    if (s2 == nullptr) {
        cudaStreamCreateWithFlags(&s2, cudaStreamNonBlocking);
        cudaEventCreateWithFlags(&ev0, cudaEventDisableTiming);
        cudaEventCreateWithFlags(&ev1, cudaEventDisableTiming);
    }

    const int edge4Blocks = (N_EDGES / 4 + 255) / 256;
    const int scanBlocks  = (N_NODES + 1023) / 1024;
    const int aggBlocks   = (N_NODES * 32 + 255) / 256;
    const int gemmBlocks  = (N_NODES + 63) / 64;

    // fork: layer-1 GEMM (no CSR dependency) runs on s2, CSR build on main stream
    cudaEventRecord(ev0, 0);
    cudaStreamWaitEvent(s2, ev0, 0);
    k_gemm_tp1<<<gemmBlocks, 512, 0, s2>>>(in_feat, W1, b1);
    cudaEventRecord(ev1, s2);

    // CSR build chain (main stream)
    void* degPtr = nullptr;
    cudaGetSymbolAddress(&degPtr, g_deg);
    cudaMemsetAsync(degPtr, 0, N_NODES * sizeof(int));
    k_deg<<<edge4Blocks, 256>>>((const int4*)dst);
    k_scan_local<<<scanBlocks, 1024>>>();
    k_scan_finish<<<scanBlocks, 256>>>();
    k_fill_csr<<<edge4Blocks, 256>>>((const int4*)src, (const int4*)dst,
                                     (const float4*)edge_feat);

    // join: aggregation needs CSR + tp1
    cudaStreamWaitEvent(0, ev1, 0);
    k_agg64_relu<<<aggBlocks, 256>>>();

    // layer 2
    k_gemm2<<<gemmBlocks, 256>>>(W2, b2);
    k_agg32_out<<<aggBlocks, 256>>>(out);
}

// round 6
// speedup vs baseline: 1.0108x; 1.0108x over previous
#include <cuda_runtime.h>
#include <cstdint>

#define N_NODES 100000
#define N_EDGES 1600000
#define F 64
#define SCAN_BLOCKS ((N_NODES + 1023) / 1024)   // 98

// ---------------- static device scratch ----------------
__device__ int   g_deg[N_NODES];
__device__ int   g_off[N_NODES + 1];
__device__ int   g_cursor[N_NODES];
__device__ unsigned long long g_state[SCAN_BLOCKS];   // decoupled-lookback state
__device__ int2  g_csr[N_EDGES];              // packed {src, float_bits(e)}
__device__ float g_deginv[N_NODES];
__device__ float g_hN[(size_t)N_NODES * F];   // hN (layer1) / tp2 (layer2, reused)
__device__ float g_h1[(size_t)N_NODES * F];   // layer-1 output

// ---------------- f32x2 packed-FMA helpers (Blackwell FFMA2) ----------------
__device__ __forceinline__ unsigned long long pack2(float a) {
    unsigned long long r;
    asm("mov.b64 %0, {%1, %1};" : "=l"(r) : "f"(a));
    return r;
}
__device__ __forceinline__ void ffma2(unsigned long long& d,
                                      unsigned long long a, unsigned long long b) {
    asm("fma.rn.f32x2 %0, %1, %2, %0;" : "+l"(d) : "l"(a), "l"(b));
}
__device__ __forceinline__ float2 unpack2(unsigned long long v) {
    float lo, hi;
    asm("mov.b64 {%0, %1}, %2;" : "=f"(lo), "=f"(hi) : "l"(v));
    return make_float2(lo, hi);
}

// ---------------- CSR build ----------------
__global__ void k_deg(const int4* __restrict__ dst4) {
    int i = blockIdx.x * blockDim.x + threadIdx.x;
    if (i < N_EDGES / 4) {
        int4 d = dst4[i];
        atomicAdd(&g_deg[d.x], 1);
        atomicAdd(&g_deg[d.y], 1);
        atomicAdd(&g_deg[d.z], 1);
        atomicAdd(&g_deg[d.w], 1);
    }
}

// single-pass decoupled-lookback scan over degrees; writes off/cursor/deginv.
// status: 0 = invalid, 1 = aggregate, 2 = inclusive prefix. Packed (status<<32)|value.
__global__ void __launch_bounds__(1024) k_scan_lookback() {
    __shared__ int sh[1024];
    __shared__ int s_prefix;
    int b = blockIdx.x, t = threadIdx.x;
    int i = b * 1024 + t;
    int v = (i < N_NODES) ? g_deg[i] : 0;
    sh[t] = v;
    __syncthreads();
#pragma unroll
    for (int off = 1; off < 1024; off <<= 1) {
        int x = 0;
        if (t >= off) x = sh[t - off];
        __syncthreads();
        sh[t] += x;
        __syncthreads();
    }
    int aggregate = sh[1023];

    if (t == 0) {
        unsigned st0 = (b == 0) ? 2u : 1u;
        atomicExch(&g_state[b], ((unsigned long long)st0 << 32) | (unsigned)aggregate);
        if (b == 0) s_prefix = 0;
    }
    __syncwarp(0xffffffff);

    if (b > 0 && t < 32) {
        int prefix = 0;
        int base = b - 1;
        bool done = false;
        while (!done) {
            int j = base - t;
            unsigned long long s = (j >= 0) ? atomicAdd(&g_state[j], 0ull)
                                            : (2ull << 32);
            unsigned st = (unsigned)(s >> 32);
            if (__all_sync(0xffffffff, st != 0)) {
                unsigned mask = __ballot_sync(0xffffffff, st == 2);
                int val = (j >= 0) ? (int)(unsigned)s : 0;
                if (mask) {
                    int lead = __ffs(mask) - 1;   // nearest status-2 block
                    if (t > lead) val = 0;        // beyond it: already covered
                    done = true;
                }
#pragma unroll
                for (int o = 16; o; o >>= 1) val += __shfl_xor_sync(0xffffffff, val, o);
                prefix += val;
                if (!done) base -= 32;
            }
        }
        if (t == 0) {
            atomicExch(&g_state[b],
                       (2ull << 32) | (unsigned)(prefix + aggregate));
            s_prefix = prefix;
        }
    }
    __syncthreads();

    int prefix = s_prefix;
    if (i < N_NODES) {
        int val = sh[t] + prefix;
        g_off[i + 1] = val;
        int d = g_deg[i];
        g_cursor[i] = val - d;                // == final g_off[i]
        g_deginv[i] = 1.0f / (float)(d > 0 ? d : 1);
    }
    if (i == 0) g_off[0] = 0;
}

__global__ void k_fill_csr(const int4* __restrict__ src4, const int4* __restrict__ dst4,
                           const float4* __restrict__ e4) {
    int i = blockIdx.x * blockDim.x + threadIdx.x;
    if (i < N_EDGES / 4) {
        int4 s = src4[i];
        int4 d = dst4[i];
        float4 e = e4[i];
        int p0 = atomicAdd(&g_cursor[d.x], 1);
        g_csr[p0] = make_int2(s.x, __float_as_int(e.x));
        int p1 = atomicAdd(&g_cursor[d.y], 1);
        g_csr[p1] = make_int2(s.y, __float_as_int(e.y));
        int p2 = atomicAdd(&g_cursor[d.z], 1);
        g_csr[p2] = make_int2(s.z, __float_as_int(e.z));
        int p3 = atomicAdd(&g_cursor[d.w], 1);
        g_csr[p3] = make_int2(s.w, __float_as_int(e.w));
    }
}

// ---------------- aggregation layer 1: 64 feats, 2 edges per warp-step ----------------
__global__ void __launch_bounds__(256) k_agg64(const float* __restrict__ h) {
    int warp = (blockIdx.x * blockDim.x + threadIdx.x) >> 5;
    if (warp >= N_NODES) return;
    int lane = threadIdx.x & 31;
    int g = lane >> 4;      // edge sub-group 0..1
    int c = lane & 15;      // float4 slot

    int beg = g_off[warp], end = g_off[warp + 1];
    float4 acc = make_float4(0.f, 0.f, 0.f, 0.f);
#pragma unroll 4
    for (int p = beg; p < end; p += 2) {
        int pe = p + g;
        if (pe < end) {
            int2 se = g_csr[pe];
            float ev = __int_as_float(se.y);
            float4 r = *(const float4*)(h + (size_t)se.x * F + c * 4);
            acc.x = fmaf(r.x, ev, acc.x);
            acc.y = fmaf(r.y, ev, acc.y);
            acc.z = fmaf(r.z, ev, acc.z);
            acc.w = fmaf(r.w, ev, acc.w);
        }
    }
    acc.x += __shfl_xor_sync(0xffffffff, acc.x, 16);
    acc.y += __shfl_xor_sync(0xffffffff, acc.y, 16);
    acc.z += __shfl_xor_sync(0xffffffff, acc.z, 16);
    acc.w += __shfl_xor_sync(0xffffffff, acc.w, 16);
    if (g == 0) {
        float dinv = g_deginv[warp];
        float4 o = make_float4(acc.x * dinv, acc.y * dinv, acc.z * dinv, acc.w * dinv);
        *(float4*)(g_hN + (size_t)warp * F + c * 4) = o;
    }
}

// ---------------- layer-2 aggregation + epilogue: 32 feats, 4 edges per step ----------------
// tp2 (= g_hN): tp2[n][0..31] = h1@W2_top + b2, tp2[n][32..63] = h1@W2_bot
// out[n][j] = tp2[n][j] + dinv * sum_e tp2[src][32+j]*e
__global__ void __launch_bounds__(256) k_agg32_out(float* __restrict__ out) {
    int warp = (blockIdx.x * blockDim.x + threadIdx.x) >> 5;
    if (warp >= N_NODES) return;
    int lane = threadIdx.x & 31;
    int g = lane >> 3;      // edge sub-group 0..3
    int c = lane & 7;       // float4 slot

    const float* __restrict__ tp = (const float*)g_hN;

    int beg = g_off[warp], end = g_off[warp + 1];
    float4 acc = make_float4(0.f, 0.f, 0.f, 0.f);
#pragma unroll 4
    for (int p = beg; p < end; p += 4) {
        int pe = p + g;
        if (pe < end) {
            int2 se = g_csr[pe];
            float ev = __int_as_float(se.y);
            float4 r = *(const float4*)(tp + (size_t)se.x * 64 + 32 + c * 4);
            acc.x = fmaf(r.x, ev, acc.x);
            acc.y = fmaf(r.y, ev, acc.y);
            acc.z = fmaf(r.z, ev, acc.z);
            acc.w = fmaf(r.w, ev, acc.w);
        }
    }
    acc.x += __shfl_xor_sync(0xffffffff, acc.x, 8);
    acc.y += __shfl_xor_sync(0xffffffff, acc.y, 8);
    acc.z += __shfl_xor_sync(0xffffffff, acc.z, 8);
    acc.w += __shfl_xor_sync(0xffffffff, acc.w, 8);
    acc.x += __shfl_xor_sync(0xffffffff, acc.x, 16);
    acc.y += __shfl_xor_sync(0xffffffff, acc.y, 16);
    acc.z += __shfl_xor_sync(0xffffffff, acc.z, 16);
    acc.w += __shfl_xor_sync(0xffffffff, acc.w, 16);
    if (g == 0) {
        float dinv = g_deginv[warp];
        float4 t = *(const float4*)(tp + (size_t)warp * 64 + c * 4);
        float4 o = make_float4(t.x + acc.x * dinv, t.y + acc.y * dinv,
                               t.z + acc.z * dinv, t.w + acc.w * dinv);
        *(float4*)(out + (size_t)warp * 32 + c * 4) = o;
    }
}

// ---------------- layer-1 GEMM (f32x2): h1 = relu([in | hN] @ W1 + b1) ----------------
__global__ void __launch_bounds__(256) k_gemm1(const float* __restrict__ A0,
                                               const float* __restrict__ W,
                                               const float* __restrict__ bias) {
    constexpr int NOUT = 64;
    constexpr int BM = 64;
    constexpr int JG = NOUT / 4;   // 16
    constexpr int NT = 256;
    constexpr int AP = 68;

    __shared__ __align__(16) float sA[BM * AP];
    __shared__ __align__(16) float sW[64 * NOUT];

    int tid = threadIdx.x;
    int m0  = blockIdx.x * BM;
    int jg  = tid % JG;
    int ng  = tid / JG;

    unsigned long long acc[4][2];
    {
        ulonglong2 b2v = *(const ulonglong2*)(bias + jg * 4);
#pragma unroll
        for (int i = 0; i < 4; i++) { acc[i][0] = b2v.x; acc[i][1] = b2v.y; }
    }

#pragma unroll
    for (int half = 0; half < 2; ++half) {
        const float* __restrict__ Asrc = half ? (const float*)g_hN : A0;
        for (int idx = tid; idx < BM * 16; idx += NT) {
            int m = idx >> 4, kq = idx & 15;
            int gm = m0 + m;
            float4 v = make_float4(0.f, 0.f, 0.f, 0.f);
            if (gm < N_NODES) v = *(const float4*)(Asrc + (size_t)gm * F + kq * 4);
            *(float4*)(sA + m * AP + kq * 4) = v;
        }
        for (int idx = tid; idx < 64 * NOUT / 4; idx += NT) {
            *(float4*)(sW + idx * 4) = *(const float4*)(W + half * 64 * NOUT + idx * 4);
        }
        __syncthreads();

        const float* a_base = sA + (ng * 4) * AP;
#pragma unroll 8
        for (int k = 0; k < 64; ++k) {
            ulonglong2 w2 = *(const ulonglong2*)(sW + k * NOUT + jg * 4);
            unsigned long long a0 = pack2(a_base[k]);
            unsigned long long a1 = pack2(a_base[AP + k]);
            unsigned long long a2 = pack2(a_base[2 * AP + k]);
            unsigned long long a3 = pack2(a_base[3 * AP + k]);
            ffma2(acc[0][0], a0, w2.x); ffma2(acc[0][1], a0, w2.y);
            ffma2(acc[1][0], a1, w2.x); ffma2(acc[1][1], a1, w2.y);
            ffma2(acc[2][0], a2, w2.x); ffma2(acc[2][1], a2, w2.y);
            ffma2(acc[3][0], a3, w2.x); ffma2(acc[3][1], a3, w2.y);
        }
        __syncthreads();
    }

#pragma unroll
    for (int i = 0; i < 4; i++) {
        int gm = m0 + ng * 4 + i;
        if (gm < N_NODES) {
            float2 lo = unpack2(acc[i][0]);
            float2 hi = unpack2(acc[i][1]);
            float4 o = make_float4(fmaxf(lo.x, 0.f), fmaxf(lo.y, 0.f),
                                   fmaxf(hi.x, 0.f), fmaxf(hi.y, 0.f));
            *(float4*)(g_h1 + (size_t)gm * NOUT + jg * 4) = o;
        }
    }
}

// ---------------- layer-2 GEMM (f32x2, combined): tp2 = [h1@W2_top + b2 | h1@W2_bot] ----------------
__global__ void __launch_bounds__(256) k_gemm2(const float* __restrict__ W2,
                                               const float* __restrict__ b2) {
    constexpr int NOUT = 64;
    constexpr int BM = 64;
    constexpr int JG = NOUT / 4;   // 16
    constexpr int NT = 256;
    constexpr int AP = 68;

    __shared__ __align__(16) float sA[BM * AP];
    __shared__ __align__(16) float sW[64 * NOUT];

    int tid = threadIdx.x;
    int m0  = blockIdx.x * BM;
    int jg  = tid % JG;
    int ng  = tid / JG;

    unsigned long long acc[4][2];
    if (jg < 8) {
        ulonglong2 b2v = *(const ulonglong2*)(b2 + jg * 4);
#pragma unroll
        for (int i = 0; i < 4; i++) { acc[i][0] = b2v.x; acc[i][1] = b2v.y; }
    } else {
#pragma unroll
        for (int i = 0; i < 4; i++) { acc[i][0] = 0ull; acc[i][1] = 0ull; }
    }

    for (int idx = tid; idx < BM * 16; idx += NT) {
        int m = idx >> 4, kq = idx & 15;
        int gm = m0 + m;
        float4 v = make_float4(0.f, 0.f, 0.f, 0.f);
        if (gm < N_NODES) v = *(const float4*)(g_h1 + (size_t)gm * F + kq * 4);
        *(float4*)(sA + m * AP + kq * 4) = v;
    }
    for (int idx = tid; idx < 64 * NOUT / 4; idx += NT) {
        int k = idx >> 4, jq = idx & 15;
        float4 v;
        if (jq < 8) v = *(const float4*)(W2 + k * 32 + jq * 4);
        else        v = *(const float4*)(W2 + (64 + k) * 32 + (jq - 8) * 4);
        *(float4*)(sW + k * NOUT + jq * 4) = v;
    }
    __syncthreads();

    const float* a_base = sA + (ng * 4) * AP;
#pragma unroll 8
    for (int k = 0; k < 64; ++k) {
        ulonglong2 w2 = *(const ulonglong2*)(sW + k * NOUT + jg * 4);
        unsigned long long a0 = pack2(a_base[k]);
        unsigned long long a1 = pack2(a_base[AP + k]);
        unsigned long long a2 = pack2(a_base[2 * AP + k]);
        unsigned long long a3 = pack2(a_base[3 * AP + k]);
        ffma2(acc[0][0], a0, w2.x); ffma2(acc[0][1], a0, w2.y);
        ffma2(acc[1][0], a1, w2.x); ffma2(acc[1][1], a1, w2.y);
        ffma2(acc[2][0], a2, w2.x); ffma2(acc[2][1], a2, w2.y);
        ffma2(acc[3][0], a3, w2.x); ffma2(acc[3][1], a3, w2.y);
    }

#pragma unroll
    for (int i = 0; i < 4; i++) {
        int gm = m0 + ng * 4 + i;
        if (gm < N_NODES) {
            float2 lo = unpack2(acc[i][0]);
            float2 hi = unpack2(acc[i][1]);
            float4 o = make_float4(lo.x, lo.y, hi.x, hi.y);
            *(float4*)(g_hN + (size_t)gm * NOUT + jg * 4) = o;   // tp2 stored in g_hN
        }
    }
}

// ---------------- launch ----------------
extern "C" void kernel_launch(void* const* d_in, const int* in_sizes, int n_in,
                              void* d_out, int out_size) {
    const float* in_feat   = (const float*)d_in[0];
    const float* edge_feat = (const float*)d_in[1];
    const int*   src       = (const int*)d_in[2];
    const int*   dst       = (const int*)d_in[3];
    const float* W1        = (const float*)d_in[4];
    const float* b1        = (const float*)d_in[5];
    const float* W2        = (const float*)d_in[6];
    const float* b2        = (const float*)d_in[7];
    float*       out       = (float*)d_out;

    const int edge4Blocks = (N_EDGES / 4 + 255) / 256;
    const int aggBlocks   = (N_NODES * 32 + 255) / 256;
    const int gemmBlocks  = (N_NODES + 63) / 64;

    // zero degree + lookback state via memset DMA nodes (no kernel launches)
    void* degPtr = nullptr;
    void* statePtr = nullptr;
    cudaGetSymbolAddress(&degPtr, g_deg);
    cudaGetSymbolAddress(&statePtr, g_state);
    cudaMemsetAsync(degPtr, 0, N_NODES * sizeof(int));
    cudaMemsetAsync(statePtr, 0, SCAN_BLOCKS * sizeof(unsigned long long));

    // CSR build: deg -> single-pass scan -> fill
    k_deg<<<edge4Blocks, 256>>>((const int4*)dst);
    k_scan_lookback<<<SCAN_BLOCKS, 1024>>>();
    k_fill_csr<<<edge4Blocks, 256>>>((const int4*)src, (const int4*)dst,
                                     (const float4*)edge_feat);

    // Layer 1: hN = Agg(in); h1 = relu([in | hN] @ W1 + b1)
    k_agg64<<<aggBlocks, 256>>>(in_feat);
    k_gemm1<<<gemmBlocks, 256>>>(in_feat, W1, b1);

    // Layer 2 (project-then-aggregate): tp2 = [h1@W2_top+b2 | h1@W2_bot]
    // out = tp2_top + Agg(tp2_bot)
    k_gemm2<<<gemmBlocks, 256>>>(W2, b2);
    k_agg32_out<<<aggBlocks, 256>>>(out);
}

// round 7
// speedup vs baseline: 1.0132x; 1.0023x over previous
#include <cuda_runtime.h>
#include <cuda_bf16.h>
#include <cstdint>

#define N_NODES 100000
#define N_EDGES 1600000
#define F 64
#define EDGE4BLOCKS ((N_EDGES / 4 + 255) / 256)          // 1563
#define CVTBLOCKS   ((N_NODES * F / 8 + 255) / 256)      // 3125

// ---------------- static device scratch ----------------
__device__ int      g_deg[N_NODES];
__device__ int      g_off[N_NODES + 1];
__device__ int      g_cursor[N_NODES];
__device__ int      g_bsum[128];
__device__ int2     g_csr[N_EDGES];               // packed {src, float_bits(e)}
__device__ float    g_deginv[N_NODES];
__device__ unsigned g_inb[(size_t)N_NODES * 32];  // in_feat as bf16x2 (row = 128B)
__device__ float    g_hN[(size_t)N_NODES * F];    // layer-1 aggregated (fp32)
__device__ float    g_h1[(size_t)N_NODES * F];    // layer-1 output
__device__ float    g_tpt[(size_t)N_NODES * 32];  // tp_top = h1@W2_top + b2 (fp32)
__device__ unsigned g_tpb[(size_t)N_NODES * 16];  // tp_bot = h1@W2_bot (bf16x2, row = 64B)

// ---------------- helpers ----------------
__device__ __forceinline__ unsigned long long pack2(float a) {
    unsigned long long r;
    asm("mov.b64 %0, {%1, %1};" : "=l"(r) : "f"(a));
    return r;
}
__device__ __forceinline__ void ffma2(unsigned long long& d,
                                      unsigned long long a, unsigned long long b) {
    asm("fma.rn.f32x2 %0, %1, %2, %0;" : "+l"(d) : "l"(a), "l"(b));
}
__device__ __forceinline__ float2 unpack2(unsigned long long v) {
    float lo, hi;
    asm("mov.b64 {%0, %1}, %2;" : "=f"(lo), "=f"(hi) : "l"(v));
    return make_float2(lo, hi);
}
__device__ __forceinline__ unsigned bf2(float a, float b) {
    __nv_bfloat162 h = __floats2bfloat162_rn(a, b);
    return *reinterpret_cast<unsigned*>(&h);
}
__device__ __forceinline__ float2 unbf2(unsigned u) {
    __nv_bfloat162 h = *reinterpret_cast<__nv_bfloat162*>(&u);
    return __bfloat1622float2(h);
}

// ---------------- prep: degree histogram + bf16 conversion of in_feat ----------------
__global__ void k_prep(const int4* __restrict__ dst4, const float4* __restrict__ inf) {
    int b = blockIdx.x, t = threadIdx.x;
    if (b < EDGE4BLOCKS) {
        int i = b * 256 + t;
        if (i < N_EDGES / 4) {
            int4 d = dst4[i];
            atomicAdd(&g_deg[d.x], 1);
            atomicAdd(&g_deg[d.y], 1);
            atomicAdd(&g_deg[d.z], 1);
            atomicAdd(&g_deg[d.w], 1);
        }
    } else {
        int i = (b - EDGE4BLOCKS) * 256 + t;    // each handles 8 floats -> 16B bf16
        if (i < N_NODES * F / 8) {
            float4 v0 = inf[(size_t)i * 2];
            float4 v1 = inf[(size_t)i * 2 + 1];
            uint4 st;
            st.x = bf2(v0.x, v0.y);
            st.y = bf2(v0.z, v0.w);
            st.z = bf2(v1.x, v1.y);
            st.w = bf2(v1.z, v1.w);
            *(uint4*)(g_inb + (size_t)i * 4) = st;
        }
    }
}

// ---------------- scan chain (round-4 proven version) ----------------
__global__ void k_scan_local() {
    __shared__ int sh[1024];
    int i = blockIdx.x * 1024 + threadIdx.x;
    int v = (i < N_NODES) ? g_deg[i] : 0;
    sh[threadIdx.x] = v;
    __syncthreads();
#pragma unroll
    for (int off = 1; off < 1024; off <<= 1) {
        int t = 0;
        if ((int)threadIdx.x >= off) t = sh[threadIdx.x - off];
        __syncthreads();
        sh[threadIdx.x] += t;
        __syncthreads();
    }
    if (i < N_NODES) g_off[i + 1] = sh[threadIdx.x];
    if (threadIdx.x == 1023) g_bsum[blockIdx.x] = sh[1023];
}

__global__ void k_scan_bsum(int nb) {
    __shared__ int sh[128];
    int t = threadIdx.x;
    int v = (t < nb) ? g_bsum[t] : 0;
    sh[t] = v;
    __syncthreads();
#pragma unroll
    for (int off = 1; off < 128; off <<= 1) {
        int x = 0;
        if (t >= off) x = sh[t - off];
        __syncthreads();
        sh[t] += x;
        __syncthreads();
    }
    if (t < nb) g_bsum[t] = sh[t];
}

__global__ void k_scan_add_cursor() {
    int i = blockIdx.x * blockDim.x + threadIdx.x;
    if (i < N_NODES) {
        int b = i >> 10;
        int val = g_off[i + 1];
        if (b > 0) val += g_bsum[b - 1];
        g_off[i + 1] = val;
        int d = g_deg[i];
        g_cursor[i] = val - d;                 // == final g_off[i]
        g_deginv[i] = 1.0f / (float)(d > 0 ? d : 1);
    }
    if (i == 0) g_off[0] = 0;
}

__global__ void k_fill_csr(const int4* __restrict__ src4, const int4* __restrict__ dst4,
                           const float4* __restrict__ e4) {
    int i = blockIdx.x * blockDim.x + threadIdx.x;
    if (i < N_EDGES / 4) {
        int4 s = src4[i];
        int4 d = dst4[i];
        float4 e = e4[i];
        int p0 = atomicAdd(&g_cursor[d.x], 1);
        g_csr[p0] = make_int2(s.x, __float_as_int(e.x));
        int p1 = atomicAdd(&g_cursor[d.y], 1);
        g_csr[p1] = make_int2(s.y, __float_as_int(e.y));
        int p2 = atomicAdd(&g_cursor[d.z], 1);
        g_csr[p2] = make_int2(s.z, __float_as_int(e.z));
        int p3 = atomicAdd(&g_cursor[d.w], 1);
        g_csr[p3] = make_int2(s.w, __float_as_int(e.w));
    }
}

// ---------------- aggregation layer 1 (bf16 gather): 64 feats, 2 edges per warp-step ----------------
__global__ void __launch_bounds__(256) k_agg64() {
    int warp = (blockIdx.x * blockDim.x + threadIdx.x) >> 5;
    if (warp >= N_NODES) return;
    int lane = threadIdx.x & 31;
    int g = lane >> 4;      // edge sub-group 0..1
    int c = lane & 15;      // uint2 slot (4 bf16 feats each)

    int beg = g_off[warp], end = g_off[warp + 1];
    float4 acc = make_float4(0.f, 0.f, 0.f, 0.f);
#pragma unroll 4
    for (int p = beg; p < end; p += 2) {
        int pe = p + g;
        if (pe < end) {
            int2 se = g_csr[pe];
            float ev = __int_as_float(se.y);
            uint2 rb = *(const uint2*)(g_inb + (size_t)se.x * 32 + c * 2);
            float2 r01 = unbf2(rb.x);
            float2 r23 = unbf2(rb.y);
            acc.x = fmaf(r01.x, ev, acc.x);
            acc.y = fmaf(r01.y, ev, acc.y);
            acc.z = fmaf(r23.x, ev, acc.z);
            acc.w = fmaf(r23.y, ev, acc.w);
        }
    }
    acc.x += __shfl_xor_sync(0xffffffff, acc.x, 16);
    acc.y += __shfl_xor_sync(0xffffffff, acc.y, 16);
    acc.z += __shfl_xor_sync(0xffffffff, acc.z, 16);
    acc.w += __shfl_xor_sync(0xffffffff, acc.w, 16);
    if (g == 0) {
        float dinv = g_deginv[warp];
        float4 o = make_float4(acc.x * dinv, acc.y * dinv, acc.z * dinv, acc.w * dinv);
        *(float4*)(g_hN + (size_t)warp * F + c * 4) = o;
    }
}

// ---------------- layer-2 aggregation + epilogue (bf16 gather): 32 feats, 4 edges per step ----------------
// out[n][j] = tpt[n][j] + dinv * sum_e e * tpb[src][j]
__global__ void __launch_bounds__(256) k_agg32_out(float* __restrict__ out) {
    int warp = (blockIdx.x * blockDim.x + threadIdx.x) >> 5;
    if (warp >= N_NODES) return;
    int lane = threadIdx.x & 31;
    int g = lane >> 3;      // edge sub-group 0..3
    int c = lane & 7;       // uint2 slot (4 bf16 feats each)

    int beg = g_off[warp], end = g_off[warp + 1];
    float4 acc = make_float4(0.f, 0.f, 0.f, 0.f);
#pragma unroll 4
    for (int p = beg; p < end; p += 4) {
        int pe = p + g;
        if (pe < end) {
            int2 se = g_csr[pe];
            float ev = __int_as_float(se.y);
            uint2 rb = *(const uint2*)(g_tpb + (size_t)se.x * 16 + c * 2);
            float2 r01 = unbf2(rb.x);
            float2 r23 = unbf2(rb.y);
            acc.x = fmaf(r01.x, ev, acc.x);
            acc.y = fmaf(r01.y, ev, acc.y);
            acc.z = fmaf(r23.x, ev, acc.z);
            acc.w = fmaf(r23.y, ev, acc.w);
        }
    }
    acc.x += __shfl_xor_sync(0xffffffff, acc.x, 8);
    acc.y += __shfl_xor_sync(0xffffffff, acc.y, 8);
    acc.z += __shfl_xor_sync(0xffffffff, acc.z, 8);
    acc.w += __shfl_xor_sync(0xffffffff, acc.w, 8);
    acc.x += __shfl_xor_sync(0xffffffff, acc.x, 16);
    acc.y += __shfl_xor_sync(0xffffffff, acc.y, 16);
    acc.z += __shfl_xor_sync(0xffffffff, acc.z, 16);
    acc.w += __shfl_xor_sync(0xffffffff, acc.w, 16);
    if (g == 0) {
        float dinv = g_deginv[warp];
        float4 t = *(const float4*)(g_tpt + (size_t)warp * 32 + c * 4);
        float4 o = make_float4(t.x + acc.x * dinv, t.y + acc.y * dinv,
                               t.z + acc.z * dinv, t.w + acc.w * dinv);
        *(float4*)(out + (size_t)warp * 32 + c * 4) = o;
    }
}

// ---------------- layer-1 GEMM (f32x2): h1 = relu([in | hN] @ W1 + b1) ----------------
__global__ void __launch_bounds__(256) k_gemm1(const float* __restrict__ A0,
                                               const float* __restrict__ W,
                                               const float* __restrict__ bias) {
    constexpr int NOUT = 64;
    constexpr int BM = 64;
    constexpr int JG = NOUT / 4;   // 16
    constexpr int NT = 256;
    constexpr int AP = 68;

    __shared__ __align__(16) float sA[BM * AP];
    __shared__ __align__(16) float sW[64 * NOUT];

    int tid = threadIdx.x;
    int m0  = blockIdx.x * BM;
    int jg  = tid % JG;
    int ng  = tid / JG;

    unsigned long long acc[4][2];
    {
        ulonglong2 b2v = *(const ulonglong2*)(bias + jg * 4);
#pragma unroll
        for (int i = 0; i < 4; i++) { acc[i][0] = b2v.x; acc[i][1] = b2v.y; }
    }

#pragma unroll
    for (int half = 0; half < 2; ++half) {
        const float* __restrict__ Asrc = half ? (const float*)g_hN : A0;
        for (int idx = tid; idx < BM * 16; idx += NT) {
            int m = idx >> 4, kq = idx & 15;
            int gm = m0 + m;
            float4 v = make_float4(0.f, 0.f, 0.f, 0.f);
            if (gm < N_NODES) v = *(const float4*)(Asrc + (size_t)gm * F + kq * 4);
            *(float4*)(sA + m * AP + kq * 4) = v;
        }
        for (int idx = tid; idx < 64 * NOUT / 4; idx += NT) {
            *(float4*)(sW + idx * 4) = *(const float4*)(W + half * 64 * NOUT + idx * 4);
        }
        __syncthreads();

        const float* a_base = sA + (ng * 4) * AP;
#pragma unroll 8
        for (int k = 0; k < 64; ++k) {
            ulonglong2 w2 = *(const ulonglong2*)(sW + k * NOUT + jg * 4);
            unsigned long long a0 = pack2(a_base[k]);
            unsigned long long a1 = pack2(a_base[AP + k]);
            unsigned long long a2 = pack2(a_base[2 * AP + k]);
            unsigned long long a3 = pack2(a_base[3 * AP + k]);
            ffma2(acc[0][0], a0, w2.x); ffma2(acc[0][1], a0, w2.y);
            ffma2(acc[1][0], a1, w2.x); ffma2(acc[1][1], a1, w2.y);
            ffma2(acc[2][0], a2, w2.x); ffma2(acc[2][1], a2, w2.y);
            ffma2(acc[3][0], a3, w2.x); ffma2(acc[3][1], a3, w2.y);
        }
        __syncthreads();
    }

#pragma unroll
    for (int i = 0; i < 4; i++) {
        int gm = m0 + ng * 4 + i;
        if (gm < N_NODES) {
            float2 lo = unpack2(acc[i][0]);
            float2 hi = unpack2(acc[i][1]);
            float4 o = make_float4(fmaxf(lo.x, 0.f), fmaxf(lo.y, 0.f),
                                   fmaxf(hi.x, 0.f), fmaxf(hi.y, 0.f));
            *(float4*)(g_h1 + (size_t)gm * NOUT + jg * 4) = o;
        }
    }
}

// ---------------- layer-2 GEMM (f32x2): tpt = h1@W2_top + b2 (fp32), tpb = h1@W2_bot (bf16) ----------------
__global__ void __launch_bounds__(256) k_gemm2(const float* __restrict__ W2,
                                               const float* __restrict__ b2) {
    constexpr int NOUT = 64;
    constexpr int BM = 64;
    constexpr int JG = NOUT / 4;   // 16
    constexpr int NT = 256;
    constexpr int AP = 68;

    __shared__ __align__(16) float sA[BM * AP];
    __shared__ __align__(16) float sW[64 * NOUT];

    int tid = threadIdx.x;
    int m0  = blockIdx.x * BM;
    int jg  = tid % JG;
    int ng  = tid / JG;

    unsigned long long acc[4][2];
    if (jg < 8) {
        ulonglong2 b2v = *(const ulonglong2*)(b2 + jg * 4);
#pragma unroll
        for (int i = 0; i < 4; i++) { acc[i][0] = b2v.x; acc[i][1] = b2v.y; }
    } else {
#pragma unroll
        for (int i = 0; i < 4; i++) { acc[i][0] = 0ull; acc[i][1] = 0ull; }
    }

    for (int idx = tid; idx < BM * 16; idx += NT) {
        int m = idx >> 4, kq = idx & 15;
        int gm = m0 + m;
        float4 v = make_float4(0.f, 0.f, 0.f, 0.f);
        if (gm < N_NODES) v = *(const float4*)(g_h1 + (size_t)gm * F + kq * 4);
        *(float4*)(sA + m * AP + kq * 4) = v;
    }
    for (int idx = tid; idx < 64 * NOUT / 4; idx += NT) {
        int k = idx >> 4, jq = idx & 15;
        float4 v;
        if (jq < 8) v = *(const float4*)(W2 + k * 32 + jq * 4);
        else        v = *(const float4*)(W2 + (64 + k) * 32 + (jq - 8) * 4);
        *(float4*)(sW + k * NOUT + jq * 4) = v;
    }
    __syncthreads();

    const float* a_base = sA + (ng * 4) * AP;
#pragma unroll 8
    for (int k = 0; k < 64; ++k) {
        ulonglong2 w2 = *(const ulonglong2*)(sW + k * NOUT + jg * 4);
        unsigned long long a0 = pack2(a_base[k]);
        unsigned long long a1 = pack2(a_base[AP + k]);
        unsigned long long a2 = pack2(a_base[2 * AP + k]);
        unsigned long long a3 = pack2(a_base[3 * AP + k]);
        ffma2(acc[0][0], a0, w2.x); ffma2(acc[0][1], a0, w2.y);
        ffma2(acc[1][0], a1, w2.x); ffma2(acc[1][1], a1, w2.y);
        ffma2(acc[2][0], a2, w2.x); ffma2(acc[2][1], a2, w2.y);
        ffma2(acc[3][0], a3, w2.x); ffma2(acc[3][1], a3, w2.y);
    }

#pragma unroll
    for (int i = 0; i < 4; i++) {
        int gm = m0 + ng * 4 + i;
        if (gm < N_NODES) {
            float2 lo = unpack2(acc[i][0]);
            float2 hi = unpack2(acc[i][1]);
            if (jg < 8) {   // top half: fp32 + bias already included
                float4 o = make_float4(lo.x, lo.y, hi.x, hi.y);
                *(float4*)(g_tpt + (size_t)gm * 32 + jg * 4) = o;
            } else {        // bottom half: bf16
                uint2 st;
                st.x = bf2(lo.x, lo.y);
                st.y = bf2(hi.x, hi.y);
                *(uint2*)(g_tpb + (size_t)gm * 16 + (jg - 8) * 2) = st;
            }
        }
    }
}

// ---------------- launch ----------------
extern "C" void kernel_launch(void* const* d_in, const int* in_sizes, int n_in,
                              void* d_out, int out_size) {
    const float* in_feat   = (const float*)d_in[0];
    const float* edge_feat = (const float*)d_in[1];
    const int*   src       = (const int*)d_in[2];
    const int*   dst       = (const int*)d_in[3];
    const float* W1        = (const float*)d_in[4];
    const float* b1        = (const float*)d_in[5];
    const float* W2        = (const float*)d_in[6];
    const float* b2        = (const float*)d_in[7];
    float*       out       = (float*)d_out;

    const int nodeBlocks = (N_NODES + 255) / 256;
    const int scanBlocks = (N_NODES + 1023) / 1024;
    const int aggBlocks  = (N_NODES * 32 + 255) / 256;
    const int gemmBlocks = (N_NODES + 63) / 64;

    // zero degree via memset DMA node
    void* degPtr = nullptr;
    cudaGetSymbolAddress(&degPtr, g_deg);
    cudaMemsetAsync(degPtr, 0, N_NODES * sizeof(int));

    // prep: degree histogram + in_feat -> bf16 table (one kernel, two block ranges)
    k_prep<<<EDGE4BLOCKS + CVTBLOCKS, 256>>>((const int4*)dst, (const float4*)in_feat);

    // scan chain + CSR fill
    k_scan_local<<<scanBlocks, 1024>>>();
    k_scan_bsum<<<1, 128>>>(scanBlocks);
    k_scan_add_cursor<<<nodeBlocks, 256>>>();
    k_fill_csr<<<EDGE4BLOCKS, 256>>>((const int4*)src, (const int4*)dst,
                                     (const float4*)edge_feat);

    // Layer 1: hN = Agg(in_bf16); h1 = relu([in | hN] @ W1 + b1)
    k_agg64<<<aggBlocks, 256>>>();
    k_gemm1<<<gemmBlocks, 256>>>(in_feat, W1, b1);

    // Layer 2 (project-then-aggregate): tpt fp32, tpb bf16; out = tpt + Agg(tpb)
    k_gemm2<<<gemmBlocks, 256>>>(W2, b2);
    k_agg32_out<<<aggBlocks, 256>>>(out);
}